// round 5
// baseline (speedup 1.0000x reference)
#include <cuda_runtime.h>

#define DD   64
#define LL   3
#define NMAX 100000
#define EMAX 1200000

// ---------------- scratch (device globals: allocation-free) ----------------
// NOTE on g_cnt lifecycle: device globals are zero-initialized at module load.
// hist_kernel requires cnt==0 on entry; scan1_kernel re-zeroes cnt after
// reading it (so scatter's cursor starts at 0); agg_kernel re-zeroes cnt so
// the NEXT execution of the graph again sees cnt==0. Every call to
// kernel_launch therefore performs identical work on identical state.
__device__ float g_M[NMAX * DD];      // mlp(h) per node (message values)
__device__ float g_G[NMAX * DD];      // aggregated messages per node
__device__ float g_H[NMAX * DD];      // hidden state ping
__device__ float g_H2[NMAX * DD];     // hidden state pong
__device__ int   g_cnt[NMAX];         // per-node in-degree / scatter cursor
__device__ int   g_rowptr[NMAX];      // CSR row pointers (within-block exclusive)
__device__ int   g_ecol[EMAX];        // CSR column indices (src node per edge)
__device__ int   g_bsums[1024];       // scan block offsets (exclusive)

// ---------------- packed f32x2 helpers ----------------
__device__ __forceinline__ unsigned long long pack2(float a, float b) {
    unsigned long long r;
    asm("mov.b64 %0, {%1, %2};" : "=l"(r) : "f"(a), "f"(b));
    return r;
}
__device__ __forceinline__ void unpack2(unsigned long long v, float& a, float& b) {
    asm("mov.b64 {%0, %1}, %2;" : "=f"(a), "=f"(b) : "l"(v));
}
__device__ __forceinline__ void fma2(unsigned long long& d,
                                     unsigned long long a, unsigned long long b) {
    asm("fma.rn.f32x2 %0, %1, %2, %0;" : "+l"(d) : "l"(a), "l"(b));
}
__device__ __forceinline__ void lds_v2u64(unsigned addr,
                                          unsigned long long& a, unsigned long long& b) {
    asm("ld.shared.v2.u64 {%0, %1}, [%2];" : "=l"(a), "=l"(b) : "r"(addr));
}

// ---------------- CSR construction ----------------
__global__ void hist_kernel(const int* __restrict__ rows, int E) {
    int e = blockIdx.x * blockDim.x + threadIdx.x;
    if (e < E) atomicAdd(&g_cnt[rows[e]], 1);
}

// Block-local exclusive scan of degrees; also re-zeroes cnt for scatter.
__global__ void scan1_kernel(int n) {
    __shared__ int sh[1024];
    int i = blockIdx.x * 1024 + threadIdx.x;
    int v = 0;
    if (i < n) {
        v = g_cnt[i];
        g_cnt[i] = 0;           // reset cursor for scatter_kernel
    }
    sh[threadIdx.x] = v;
    __syncthreads();
    for (int off = 1; off < 1024; off <<= 1) {
        int t = (threadIdx.x >= off) ? sh[threadIdx.x - off] : 0;
        __syncthreads();
        sh[threadIdx.x] += t;
        __syncthreads();
    }
    if (i < n) g_rowptr[i] = sh[threadIdx.x] - v;       // exclusive within block
    if (threadIdx.x == 1023) g_bsums[blockIdx.x] = sh[1023];
}

// Exclusive scan of per-block sums (single block).
__global__ void scan2_kernel(int nb) {
    __shared__ int sh[1024];
    int v = (threadIdx.x < nb) ? g_bsums[threadIdx.x] : 0;
    sh[threadIdx.x] = v;
    __syncthreads();
    for (int off = 1; off < 1024; off <<= 1) {
        int t = (threadIdx.x >= off) ? sh[threadIdx.x - off] : 0;
        __syncthreads();
        sh[threadIdx.x] += t;
        __syncthreads();
    }
    if (threadIdx.x < nb) g_bsums[threadIdx.x] = sh[threadIdx.x] - v;  // exclusive
}

// Scatter with the block offset folded in (no scan3 pass needed).
__global__ void scatter_kernel(const int* __restrict__ rows,
                               const int* __restrict__ cols, int E) {
    int e = blockIdx.x * blockDim.x + threadIdx.x;
    if (e < E) {
        int r = rows[e];
        int base = g_rowptr[r] + g_bsums[r >> 10];
        int pos = base + atomicAdd(&g_cnt[r], 1);
        g_ecol[pos] = cols[e];
    }
}

// ---------------- core GEMM stage: x <- act(x @ Wsm + bsm) ----------------
__device__ __forceinline__ void stage64(float (&x)[DD], const float* wsm,
                                        const float* bsm, bool do_relu) {
    unsigned wa = (unsigned)__cvta_generic_to_shared(wsm);
    unsigned long long acc[32];
#pragma unroll
    for (int j = 0; j < 32; j++) acc[j] = pack2(bsm[2 * j], bsm[2 * j + 1]);
#pragma unroll
    for (int k = 0; k < DD; k++) {
        unsigned long long xk = pack2(x[k], x[k]);
        unsigned rowa = wa + k * DD * 4;
#pragma unroll
        for (int j = 0; j < 16; j++) {
            unsigned long long a, b;
            lds_v2u64(rowa + j * 16, a, b);
            fma2(acc[2 * j], xk, a);
            fma2(acc[2 * j + 1], xk, b);
        }
    }
#pragma unroll
    for (int j = 0; j < 32; j++) {
        float a, b;
        unpack2(acc[j], a, b);
        x[2 * j]     = do_relu ? fmaxf(a, 0.0f) : a;
        x[2 * j + 1] = do_relu ? fmaxf(b, 0.0f) : b;
    }
}

__device__ __forceinline__ void load_weights(float* w1s, float* w2s,
                                             float* b1s, float* b2s,
                                             const float* W1, const float* W2,
                                             const float* B1, const float* B2) {
    const float4* w1v = (const float4*)W1;
    const float4* w2v = (const float4*)W2;
    float4* s1 = (float4*)w1s;
    float4* s2 = (float4*)w2s;
    for (int i = threadIdx.x; i < DD * DD / 4; i += blockDim.x) {
        s1[i] = w1v[i];
        s2[i] = w2v[i];
    }
    if (threadIdx.x < DD) {
        b1s[threadIdx.x] = B1[threadIdx.x];
        b2s[threadIdx.x] = B2[threadIdx.x];
    }
}

__device__ __forceinline__ void load_row(float (&x)[DD], const float* p, int r) {
    const float4* iv = (const float4*)(p + (long)r * DD);
#pragma unroll
    for (int j = 0; j < 16; j++) {
        float4 v = iv[j];
        x[4 * j] = v.x; x[4 * j + 1] = v.y; x[4 * j + 2] = v.z; x[4 * j + 3] = v.w;
    }
}
__device__ __forceinline__ void add_row(float (&x)[DD], const float* p, int r) {
    const float4* iv = (const float4*)(p + (long)r * DD);
#pragma unroll
    for (int j = 0; j < 16; j++) {
        float4 v = iv[j];
        x[4 * j] += v.x; x[4 * j + 1] += v.y; x[4 * j + 2] += v.z; x[4 * j + 3] += v.w;
    }
}
__device__ __forceinline__ void store_row(const float (&x)[DD], float* p, int r) {
    float4* ov = (float4*)(p + (long)r * DD);
#pragma unroll
    for (int j = 0; j < 16; j++)
        ov[j] = make_float4(x[4 * j], x[4 * j + 1], x[4 * j + 2], x[4 * j + 3]);
}

// ---------------- M = mlp_l(h) (first message pass) ----------------
__global__ __launch_bounds__(128, 2)
void mlp_kernel(const float* __restrict__ in,
                const float* __restrict__ W1, const float* __restrict__ b1,
                const float* __restrict__ W2, const float* __restrict__ b2,
                float* __restrict__ out, int n) {
    __shared__ float w1s[DD * DD], w2s[DD * DD], b1sh[DD], b2sh[DD];
    load_weights(w1s, w2s, b1sh, b2sh, W1, W2, b1, b2);
    __syncthreads();

    int r = blockIdx.x * blockDim.x + threadIdx.x;
    if (r >= n) return;
    float x[DD];
    load_row(x, in, r);
    stage64(x, w1s, b1sh, true);
    stage64(x, w2s, b2sh, false);
    store_row(x, out, r);
}

// ---- fused: H = mlp_a(h+G); M = mlp_b(H) ----
__global__ __launch_bounds__(128, 2)
void fused2_kernel(const float* __restrict__ h, const float* __restrict__ G,
                   const float* __restrict__ W1a, const float* __restrict__ b1a,
                   const float* __restrict__ W2a, const float* __restrict__ b2a,
                   const float* __restrict__ W1b, const float* __restrict__ b1b,
                   const float* __restrict__ W2b, const float* __restrict__ b2b,
                   float* __restrict__ H, float* __restrict__ M, int n) {
    __shared__ float w1s[DD * DD], w2s[DD * DD], b1sh[DD], b2sh[DD];
    load_weights(w1s, w2s, b1sh, b2sh, W1a, W2a, b1a, b2a);
    __syncthreads();

    int r = blockIdx.x * blockDim.x + threadIdx.x;
    bool act = r < n;
    float x[DD];
    if (act) {
        load_row(x, h, r);
        add_row(x, G, r);
        stage64(x, w1s, b1sh, true);
        stage64(x, w2s, b2sh, false);
        store_row(x, H, r);
    }
    __syncthreads();  // all smem reads done
    load_weights(w1s, w2s, b1sh, b2sh, W1b, W2b, b1b, b2b);
    __syncthreads();
    if (act) {
        stage64(x, w1s, b1sh, true);
        stage64(x, w2s, b2sh, false);
        store_row(x, M, r);
    }
}

// ---- fused final: out = mlp_c(h+G) @ Wf + bf ----
__global__ __launch_bounds__(128, 2)
void fused_final_kernel(const float* __restrict__ h, const float* __restrict__ G,
                        const float* __restrict__ W1, const float* __restrict__ b1,
                        const float* __restrict__ W2, const float* __restrict__ b2,
                        const float* __restrict__ Wf, const float* __restrict__ bf,
                        float* __restrict__ out, int n) {
    __shared__ float w1s[DD * DD], w2s[DD * DD], b1sh[DD], b2sh[DD];
    load_weights(w1s, w2s, b1sh, b2sh, W1, W2, b1, b2);
    __syncthreads();

    int r = blockIdx.x * blockDim.x + threadIdx.x;
    bool act = r < n;
    float x[DD];
    if (act) {
        load_row(x, h, r);
        add_row(x, G, r);
        stage64(x, w1s, b1sh, true);
        stage64(x, w2s, b2sh, false);
    }
    __syncthreads();
    {   // reload Wf into w1s
        const float4* wv = (const float4*)Wf;
        float4* s1 = (float4*)w1s;
        for (int i = threadIdx.x; i < DD * DD / 4; i += blockDim.x) s1[i] = wv[i];
        if (threadIdx.x < DD) b1sh[threadIdx.x] = bf[threadIdx.x];
    }
    __syncthreads();
    if (act) {
        stage64(x, w1s, b1sh, false);
        store_row(x, out, r);
    }
}

// ---------------- gather-side segment sum: G[v] = sum_{e: row=v} M[col_e] ----
// warp per node; half-warps process alternating edges with float4 loads.
// Block offsets folded in (rowptr holds within-block exclusive prefix).
// Also re-zeroes g_cnt so the next graph execution's hist starts from 0.
__global__ __launch_bounds__(256)
void agg_kernel(const float* __restrict__ Msrc, float* __restrict__ G,
                int n, int E) {
    int t = blockIdx.x * blockDim.x + threadIdx.x;
    int w = t >> 5;
    if (w >= n) return;
    int lane = t & 31;
    if (lane == 0) g_cnt[w] = 0;
    int half = lane >> 4;   // 0 or 1
    int l16 = lane & 15;    // column group (16 lanes x float4 = 64 floats)
    int s = g_rowptr[w] + g_bsums[w >> 10];
    int e = (w == n - 1) ? E : (g_rowptr[w + 1] + g_bsums[(w + 1) >> 10]);
    float a0 = 0.f, a1 = 0.f, a2 = 0.f, a3 = 0.f;
    for (int j = s + half; j < e; j += 2) {
        int c = __ldg(&g_ecol[j]);
        float4 v = __ldg((const float4*)(Msrc + (long)c * DD) + l16);
        a0 += v.x; a1 += v.y; a2 += v.z; a3 += v.w;
    }
    a0 += __shfl_down_sync(0xffffffffu, a0, 16);
    a1 += __shfl_down_sync(0xffffffffu, a1, 16);
    a2 += __shfl_down_sync(0xffffffffu, a2, 16);
    a3 += __shfl_down_sync(0xffffffffu, a3, 16);
    if (half == 0)
        ((float4*)(G + (long)w * DD))[l16] = make_float4(a0, a1, a2, a3);
}

// ---------------- launch ----------------
extern "C" void kernel_launch(void* const* d_in, const int* in_sizes, int n_in,
                              void* d_out, int out_size) {
    const float* x  = (const float*)d_in[0];
    const int* eidx = (const int*)d_in[1];
    const float* W1 = (const float*)d_in[2];
    const float* b1 = (const float*)d_in[3];
    const float* W2 = (const float*)d_in[4];
    const float* b2 = (const float*)d_in[5];
    const float* Wf = (const float*)d_in[6];
    const float* bf = (const float*)d_in[7];

    int n = in_sizes[0] / DD;
    int E = in_sizes[1] / 2;
    const int* rows = eidx;      // destination (segment id)
    const int* cols = eidx + E;  // source (gather id)

    float *M, *G, *H, *H2;
    cudaGetSymbolAddress((void**)&M, g_M);
    cudaGetSymbolAddress((void**)&G, g_G);
    cudaGetSymbolAddress((void**)&H, g_H);
    cudaGetSymbolAddress((void**)&H2, g_H2);

    const int TB = 256;
    int nb_e = (E + TB - 1) / TB;
    int nb_scan = (n + 1023) / 1024;
    int nb_mlp = (n + 127) / 128;
    int nb_agg = (n * 32 + TB - 1) / TB;

    // ---- CSR build (4 launches; cnt lifecycle documented at g_cnt) ----
    hist_kernel<<<nb_e, TB>>>(rows, E);
    scan1_kernel<<<nb_scan, 1024>>>(n);
    scan2_kernel<<<1, 1024>>>(nb_scan);
    scatter_kernel<<<nb_e, TB>>>(rows, cols, E);

    // layer weight pointers
    const float* w1[LL]; const float* bb1[LL];
    const float* w2[LL]; const float* bb2[LL];
    for (int l = 0; l < LL; l++) {
        w1[l] = W1 + l * DD * DD; bb1[l] = b1 + l * DD;
        w2[l] = W2 + l * DD * DD; bb2[l] = b2 + l * DD;
    }

    // M0 = mlp_0(x)
    mlp_kernel<<<nb_mlp, 128>>>(x, w1[0], bb1[0], w2[0], bb2[0], M, n);
    // G0 = agg(M0)
    agg_kernel<<<nb_agg, TB>>>(M, G, n, E);
    // H1 = mlp_0(x + G0); M1 = mlp_1(H1)
    fused2_kernel<<<nb_mlp, 128>>>(x, G, w1[0], bb1[0], w2[0], bb2[0],
                                   w1[1], bb1[1], w2[1], bb2[1], H, M, n);
    // G1 = agg(M1)
    agg_kernel<<<nb_agg, TB>>>(M, G, n, E);
    // H2 = mlp_1(H1 + G1); M2 = mlp_2(H2)
    fused2_kernel<<<nb_mlp, 128>>>(H, G, w1[1], bb1[1], w2[1], bb2[1],
                                   w1[2], bb1[2], w2[2], bb2[2], H2, M, n);
    // G2 = agg(M2)
    agg_kernel<<<nb_agg, TB>>>(M, G, n, E);
    // out = mlp_2(H2 + G2) @ Wf + bf
    fused_final_kernel<<<nb_mlp, 128>>>(H2, G, w1[2], bb1[2], w2[2], bb2[2],
                                        Wf, bf, (float*)d_out, n);
}

// round 6
// speedup vs baseline: 2.0936x; 2.0936x over previous
#include <cuda_runtime.h>
#include <cuda_bf16.h>

#define DD   64
#define LL   3
#define NMAX 100000
#define EMAX 1200000
#define WSTRIDE 72   // padded bf16 row stride: bank = (36*ncol + word)%32 -> conflict-free B loads

// ---------------- scratch (device globals: allocation-free) ----------------
// g_cnt lifecycle: zero at module load; hist needs cnt==0; scan1 re-zeroes it
// after reading (scatter cursor); agg re-zeroes it for the next graph replay.
__device__ float g_M[NMAX * DD];
__device__ float g_G[NMAX * DD];
__device__ float g_H[NMAX * DD];
__device__ float g_H2[NMAX * DD];
__device__ int   g_cnt[NMAX];
__device__ int   g_rowptr[NMAX];     // within-block exclusive prefix
__device__ int   g_ecol[EMAX];
__device__ int   g_bsums[1024];      // per-block offsets (exclusive)

// ---------------- CSR construction (validated in R5) ----------------
__global__ void hist_kernel(const int* __restrict__ rows, int E) {
    int e = blockIdx.x * blockDim.x + threadIdx.x;
    if (e < E) atomicAdd(&g_cnt[rows[e]], 1);
}

__global__ void scan1_kernel(int n) {
    __shared__ int sh[1024];
    int i = blockIdx.x * 1024 + threadIdx.x;
    int v = 0;
    if (i < n) { v = g_cnt[i]; g_cnt[i] = 0; }
    sh[threadIdx.x] = v;
    __syncthreads();
    for (int off = 1; off < 1024; off <<= 1) {
        int t = (threadIdx.x >= off) ? sh[threadIdx.x - off] : 0;
        __syncthreads();
        sh[threadIdx.x] += t;
        __syncthreads();
    }
    if (i < n) g_rowptr[i] = sh[threadIdx.x] - v;
    if (threadIdx.x == 1023) g_bsums[blockIdx.x] = sh[1023];
}

__global__ void scan2_kernel(int nb) {
    __shared__ int sh[1024];
    int v = (threadIdx.x < nb) ? g_bsums[threadIdx.x] : 0;
    sh[threadIdx.x] = v;
    __syncthreads();
    for (int off = 1; off < 1024; off <<= 1) {
        int t = (threadIdx.x >= off) ? sh[threadIdx.x - off] : 0;
        __syncthreads();
        sh[threadIdx.x] += t;
        __syncthreads();
    }
    if (threadIdx.x < nb) g_bsums[threadIdx.x] = sh[threadIdx.x] - v;
}

__global__ void scatter_kernel(const int* __restrict__ rows,
                               const int* __restrict__ cols, int E) {
    int e = blockIdx.x * blockDim.x + threadIdx.x;
    if (e < E) {
        int r = rows[e];
        int base = g_rowptr[r] + g_bsums[r >> 10];
        int pos = base + atomicAdd(&g_cnt[r], 1);
        g_ecol[pos] = cols[e];
    }
}

// ---------------- bf16 helpers ----------------
__device__ __forceinline__ unsigned packbf(float lo, float hi) {
    unsigned r;
    asm("cvt.rn.bf16x2.f32 %0, %1, %2;" : "=r"(r) : "f"(hi), "f"(lo));
    return r;
}
__device__ __forceinline__ float lo_f(unsigned u) { return __uint_as_float(u << 16); }
__device__ __forceinline__ float hi_f(unsigned u) { return __uint_as_float(u & 0xffff0000u); }

__device__ __forceinline__ void mma_bf16(float* d,
        unsigned a0, unsigned a1, unsigned a2, unsigned a3,
        unsigned b0, unsigned b1) {
    asm("mma.sync.aligned.m16n8k16.row.col.f32.bf16.bf16.f32 "
        "{%0,%1,%2,%3}, {%4,%5,%6,%7}, {%8,%9}, {%0,%1,%2,%3};"
        : "+f"(d[0]), "+f"(d[1]), "+f"(d[2]), "+f"(d[3])
        : "r"(a0), "r"(a1), "r"(a2), "r"(a3), "r"(b0), "r"(b1));
}

// ---------------- weight prep: W f32 [k][n] -> smem bf16 split, transposed [n][k] ----
__device__ __forceinline__ void prep_weights(__nv_bfloat16* wh, __nv_bfloat16* wl,
                                             float* bsh, const float* __restrict__ W,
                                             const float* __restrict__ B, int tid) {
    for (int idx = tid; idx < DD * DD; idx += 128) {
        int k = idx >> 6, nn = idx & 63;
        float w = W[idx];
        __nv_bfloat16 h = __float2bfloat16(w);
        float hf = __bfloat162float(h);
        wh[nn * WSTRIDE + k] = h;
        wl[nn * WSTRIDE + k] = __float2bfloat16(w - hf);
    }
    if (tid < DD) bsh[tid] = B[tid];
}

// ---------------- one GEMM stage on tensor cores ----------------
// act[m][nb][q]: C-fragment layout for 32 rows x 64 cols per warp.
//   q0=(r,2t) q1=(r,2t+1) q2=(r+8,2t) q3=(r+8,2t+1); r=grp+16m, cols nb*8+..
__device__ __forceinline__ void stage_mma(float (&act)[2][8][4],
        const __nv_bfloat16* wh, const __nv_bfloat16* wl,
        const float* bias, int lane, bool do_relu) {
    int tig = lane & 3, grp = lane >> 2;
    float acc[2][8][4];
    const float2* b2p = (const float2*)bias;
#pragma unroll
    for (int nb = 0; nb < 8; nb++) {
        float2 bv = b2p[nb * 4 + tig];
#pragma unroll
        for (int m = 0; m < 2; m++) {
            acc[m][nb][0] = bv.x; acc[m][nb][1] = bv.y;
            acc[m][nb][2] = bv.x; acc[m][nb][3] = bv.y;
        }
    }
#pragma unroll
    for (int kb = 0; kb < 4; kb++) {
        unsigned Ah[2][4], Al[2][4];
#pragma unroll
        for (int m = 0; m < 2; m++) {
            const float* c0 = act[m][2 * kb];
            const float* c1 = act[m][2 * kb + 1];
            Ah[m][0] = packbf(c0[0], c0[1]);
            Ah[m][1] = packbf(c0[2], c0[3]);
            Ah[m][2] = packbf(c1[0], c1[1]);
            Ah[m][3] = packbf(c1[2], c1[3]);
            Al[m][0] = packbf(c0[0] - lo_f(Ah[m][0]), c0[1] - hi_f(Ah[m][0]));
            Al[m][1] = packbf(c0[2] - lo_f(Ah[m][1]), c0[3] - hi_f(Ah[m][1]));
            Al[m][2] = packbf(c1[0] - lo_f(Ah[m][2]), c1[1] - hi_f(Ah[m][2]));
            Al[m][3] = packbf(c1[2] - lo_f(Ah[m][3]), c1[3] - hi_f(Ah[m][3]));
        }
#pragma unroll
        for (int nb = 0; nb < 8; nb++) {
            int ncol = nb * 8 + grp;
            const unsigned* rh = (const unsigned*)(wh + ncol * WSTRIDE);
            const unsigned* rl = (const unsigned*)(wl + ncol * WSTRIDE);
            unsigned bh0 = rh[8 * kb + tig], bh1 = rh[8 * kb + 4 + tig];
            unsigned bl0 = rl[8 * kb + tig], bl1 = rl[8 * kb + 4 + tig];
#pragma unroll
            for (int m = 0; m < 2; m++) {
                mma_bf16(acc[m][nb], Ah[m][0], Ah[m][1], Ah[m][2], Ah[m][3], bh0, bh1);
                mma_bf16(acc[m][nb], Al[m][0], Al[m][1], Al[m][2], Al[m][3], bh0, bh1);
                mma_bf16(acc[m][nb], Ah[m][0], Ah[m][1], Ah[m][2], Ah[m][3], bl0, bl1);
            }
        }
    }
#pragma unroll
    for (int m = 0; m < 2; m++)
#pragma unroll
        for (int nb = 0; nb < 8; nb++)
#pragma unroll
            for (int q = 0; q < 4; q++)
                act[m][nb][q] = do_relu ? fmaxf(acc[m][nb][q], 0.0f) : acc[m][nb][q];
}

// act <-> gmem (row-major [n][64]) in C-fragment layout, predicated on row < n
__device__ __forceinline__ void load_act(float (&act)[2][8][4], const float* __restrict__ in,
                                         const float* __restrict__ addv,
                                         int wrow, int n, int lane, bool do_add) {
    int tig = lane & 3, grp = lane >> 2;
#pragma unroll
    for (int m = 0; m < 2; m++) {
        int ra = wrow + m * 16 + grp;
        int rb = ra + 8;
#pragma unroll
        for (int nb = 0; nb < 8; nb++) {
            int cw = nb * 4 + tig;
            float2 v = make_float2(0.f, 0.f);
            if (ra < n) {
                v = ((const float2*)(in + (size_t)ra * DD))[cw];
                if (do_add) {
                    float2 g = ((const float2*)(addv + (size_t)ra * DD))[cw];
                    v.x += g.x; v.y += g.y;
                }
            }
            act[m][nb][0] = v.x; act[m][nb][1] = v.y;
            float2 w = make_float2(0.f, 0.f);
            if (rb < n) {
                w = ((const float2*)(in + (size_t)rb * DD))[cw];
                if (do_add) {
                    float2 g = ((const float2*)(addv + (size_t)rb * DD))[cw];
                    w.x += g.x; w.y += g.y;
                }
            }
            act[m][nb][2] = w.x; act[m][nb][3] = w.y;
        }
    }
}

__device__ __forceinline__ void store_act(const float (&act)[2][8][4], float* __restrict__ dst,
                                          int wrow, int n, int lane) {
    int tig = lane & 3, grp = lane >> 2;
#pragma unroll
    for (int m = 0; m < 2; m++) {
        int ra = wrow + m * 16 + grp;
        int rb = ra + 8;
#pragma unroll
        for (int nb = 0; nb < 8; nb++) {
            int cw = nb * 4 + tig;
            if (ra < n)
                ((float2*)(dst + (size_t)ra * DD))[cw] = make_float2(act[m][nb][0], act[m][nb][1]);
            if (rb < n)
                ((float2*)(dst + (size_t)rb * DD))[cw] = make_float2(act[m][nb][2], act[m][nb][3]);
        }
    }
}

// MODE 0: out1 = mlp(in)                       (2 stages, no add)
// MODE 1: out1 = mlp_a(in+add); out2 = mlp_b(out1)   (4 stages)
// MODE 2: out1 = mlp_a(in+add) @ Wb1 + Bb1     (3 stages; Wb1=Wf)
template <int MODE>
__global__ __launch_bounds__(128, 3)
void mlp_mma_kernel(const float* __restrict__ in, const float* __restrict__ addv,
                    const float* __restrict__ Wa1, const float* __restrict__ Ba1,
                    const float* __restrict__ Wa2, const float* __restrict__ Ba2,
                    const float* __restrict__ Wb1, const float* __restrict__ Bb1,
                    const float* __restrict__ Wb2, const float* __restrict__ Bb2,
                    float* __restrict__ out1, float* __restrict__ out2,
                    int n, int row0) {
    __shared__ __align__(16) __nv_bfloat16 wh[DD * WSTRIDE];
    __shared__ __align__(16) __nv_bfloat16 wl[DD * WSTRIDE];
    __shared__ float bsh[DD];

    int tid = threadIdx.x;
    int lane = tid & 31, wid = tid >> 5;
    int wrow = row0 + blockIdx.x * 128 + wid * 32;

    float act[2][8][4];
    load_act(act, in, addv, wrow, n, lane, MODE != 0);

    prep_weights(wh, wl, bsh, Wa1, Ba1, tid);
    __syncthreads();
    stage_mma(act, wh, wl, bsh, lane, true);

    __syncthreads();
    prep_weights(wh, wl, bsh, Wa2, Ba2, tid);
    __syncthreads();
    stage_mma(act, wh, wl, bsh, lane, false);

    if (MODE == 0 || MODE == 1) store_act(act, out1, wrow, n, lane);

    if (MODE == 1) {
        __syncthreads();
        prep_weights(wh, wl, bsh, Wb1, Bb1, tid);
        __syncthreads();
        stage_mma(act, wh, wl, bsh, lane, true);

        __syncthreads();
        prep_weights(wh, wl, bsh, Wb2, Bb2, tid);
        __syncthreads();
        stage_mma(act, wh, wl, bsh, lane, false);
        store_act(act, out2, wrow, n, lane);
    }
    if (MODE == 2) {
        __syncthreads();
        prep_weights(wh, wl, bsh, Wb1, Bb1, tid);
        __syncthreads();
        stage_mma(act, wh, wl, bsh, lane, false);
        store_act(act, out1, wrow, n, lane);
    }
}

// ---------------- gather-side segment sum (validated in R5) ----------------
__global__ __launch_bounds__(256)
void agg_kernel(const float* __restrict__ Msrc, float* __restrict__ G,
                int n, int E) {
    int t = blockIdx.x * blockDim.x + threadIdx.x;
    int w = t >> 5;
    if (w >= n) return;
    int lane = t & 31;
    if (lane == 0) g_cnt[w] = 0;
    int half = lane >> 4;
    int l16 = lane & 15;
    int s = g_rowptr[w] + g_bsums[w >> 10];
    int e = (w == n - 1) ? E : (g_rowptr[w + 1] + g_bsums[(w + 1) >> 10]);
    float a0 = 0.f, a1 = 0.f, a2 = 0.f, a3 = 0.f;
    for (int j = s + half; j < e; j += 2) {
        int c = __ldg(&g_ecol[j]);
        float4 v = __ldg((const float4*)(Msrc + (size_t)c * DD) + l16);
        a0 += v.x; a1 += v.y; a2 += v.z; a3 += v.w;
    }
    a0 += __shfl_down_sync(0xffffffffu, a0, 16);
    a1 += __shfl_down_sync(0xffffffffu, a1, 16);
    a2 += __shfl_down_sync(0xffffffffu, a2, 16);
    a3 += __shfl_down_sync(0xffffffffu, a3, 16);
    if (half == 0)
        ((float4*)(G + (size_t)w * DD))[l16] = make_float4(a0, a1, a2, a3);
}

// ---------------- launch ----------------
extern "C" void kernel_launch(void* const* d_in, const int* in_sizes, int n_in,
                              void* d_out, int out_size) {
    const float* x  = (const float*)d_in[0];
    const int* eidx = (const int*)d_in[1];
    const float* W1 = (const float*)d_in[2];
    const float* b1 = (const float*)d_in[3];
    const float* W2 = (const float*)d_in[4];
    const float* b2 = (const float*)d_in[5];
    const float* Wf = (const float*)d_in[6];
    const float* bf = (const float*)d_in[7];

    int n = in_sizes[0] / DD;
    int E = in_sizes[1] / 2;
    const int* rows = eidx;
    const int* cols = eidx + E;

    float *M, *G, *H, *H2;
    cudaGetSymbolAddress((void**)&M, g_M);
    cudaGetSymbolAddress((void**)&G, g_G);
    cudaGetSymbolAddress((void**)&H, g_H);
    cudaGetSymbolAddress((void**)&H2, g_H2);

    const int TB = 256;
    int nb_e = (E + TB - 1) / TB;
    int nb_scan = (n + 1023) / 1024;
    int nb_mma = (n + 127) / 128;          // 782
    int nb_agg = (n * 32 + TB - 1) / TB;

    const float* w1[LL]; const float* bb1[LL];
    const float* w2[LL]; const float* bb2[LL];
    for (int l = 0; l < LL; l++) {
        w1[l] = W1 + l * DD * DD; bb1[l] = b1 + l * DD;
        w2[l] = W2 + l * DD * DD; bb2[l] = b2 + l * DD;
    }

    // CSR part 1
    hist_kernel<<<nb_e, TB>>>(rows, E);
    scan1_kernel<<<nb_scan, 1024>>>(n);

    // First message pass M = mlp_0(x), split into thirds (also aims ncu at MMA kernels)
    int tb1 = nb_mma / 3, tb2 = nb_mma / 3;
    int tb3 = nb_mma - tb1 - tb2;
    mlp_mma_kernel<0><<<tb1, 128>>>(x, nullptr, w1[0], bb1[0], w2[0], bb2[0],
                                    nullptr, nullptr, nullptr, nullptr, M, nullptr, n, 0);
    mlp_mma_kernel<0><<<tb2, 128>>>(x, nullptr, w1[0], bb1[0], w2[0], bb2[0],
                                    nullptr, nullptr, nullptr, nullptr, M, nullptr,
                                    n, tb1 * 128);
    mlp_mma_kernel<0><<<tb3, 128>>>(x, nullptr, w1[0], bb1[0], w2[0], bb2[0],
                                    nullptr, nullptr, nullptr, nullptr, M, nullptr,
                                    n, (tb1 + tb2) * 128);

    // CSR part 2
    scan2_kernel<<<1, 1024>>>(nb_scan);
    scatter_kernel<<<nb_e, TB>>>(rows, cols, E);

    // layer 0 -> 1
    agg_kernel<<<nb_agg, TB>>>(M, G, n, E);
    mlp_mma_kernel<1><<<nb_mma, 128>>>(x, G, w1[0], bb1[0], w2[0], bb2[0],
                                       w1[1], bb1[1], w2[1], bb2[1], H, M, n, 0);
    // layer 1 -> 2
    agg_kernel<<<nb_agg, TB>>>(M, G, n, E);
    mlp_mma_kernel<1><<<nb_mma, 128>>>(H, G, w1[1], bb1[1], w2[1], bb2[1],
                                       w1[2], bb1[2], w2[2], bb2[2], H2, M, n, 0);
    // layer 2 + final projection
    agg_kernel<<<nb_agg, TB>>>(M, G, n, E);
    mlp_mma_kernel<2><<<nb_mma, 128>>>(H2, G, w1[2], bb1[2], w2[2], bb2[2],
                                       Wf, bf, nullptr, nullptr, (float*)d_out, nullptr, n, 0);
}